// round 5
// baseline (speedup 1.0000x reference)
#include <cuda_runtime.h>

// Problem constants
constexpr int kB = 512;   // batch
constexpr int kL = 128;   // seq len
constexpr int kD = 128;   // model dim
// H = 4 heads of 32

// Scratch (device globals: allocation-free rule)
__device__ float    g_x [kB * kL * kD];               // residual stream, [b][t][d]
__device__ unsigned g_xn[kB * kL * kD];               // LN output, tf32 bit patterns
__device__ float    g_h [kB * kL * kD];               // raw scan output h
__device__ float    g_pre[(size_t)kL * kB * 4 * kD];  // gate preacts, [t][b][g][d]
__device__ unsigned g_Wt[2 * 4 * kD * kD];            // W rounded to tf32

typedef unsigned long long ull;

__device__ __forceinline__ ull pack2(float lo, float hi) {
    ull r; asm("mov.b64 %0,{%1,%2};" : "=l"(r) : "f"(lo), "f"(hi)); return r;
}
__device__ __forceinline__ void unpack2(ull v, float& lo, float& hi) {
    asm("mov.b64 {%0,%1},%2;" : "=f"(lo), "=f"(hi) : "l"(v));
}
__device__ __forceinline__ ull ffma2(ull a, ull b, ull c) {
    ull d; asm("fma.rn.f32x2 %0,%1,%2,%3;" : "=l"(d) : "l"(a), "l"(b), "l"(c)); return d;
}
__device__ __forceinline__ float tanh_fast(float x) {
    float y; asm("tanh.approx.f32 %0,%1;" : "=f"(y) : "f"(x)); return y;
}
__device__ __forceinline__ unsigned to_tf32(float f) {
    unsigned u; asm("cvt.rna.tf32.f32 %0, %1;" : "=r"(u) : "f"(f)); return u;
}

__device__ __forceinline__ void cp_async16(unsigned smem, const void* gptr) {
    asm volatile("cp.async.cg.shared.global [%0], [%1], 16;" :: "r"(smem), "l"(gptr));
}
__device__ __forceinline__ void cp_commit() {
    asm volatile("cp.async.commit_group;");
}
template<int N>
__device__ __forceinline__ void cp_wait() {
    asm volatile("cp.async.wait_group %0;" :: "n"(N));
}

// ---------------------------------------------------------------------------
// W -> tf32 pre-round (both layers, once per launch)
// ---------------------------------------------------------------------------
__global__ void k_wcvt(const float* __restrict__ Wg) {
    int i = blockIdx.x * 256 + threadIdx.x;     // 32768 threads x 4 elems
    #pragma unroll
    for (int j = 0; j < 4; j++) {
        int e = i * 4 + j;
        g_Wt[e] = to_tf32(__ldg(&Wg[e]));
    }
}

// ---------------------------------------------------------------------------
// Fused embedding gather + LayerNorm(layer0). One warp per row of 128.
// g_x = emb[id]; g_xn = tf32(LN(emb[id])).
// ---------------------------------------------------------------------------
__global__ void k_embed_ln(const int* __restrict__ ids, const float4* __restrict__ emb,
                           const float* __restrict__ w, const float* __restrict__ bb) {
    int t    = blockIdx.x * 256 + threadIdx.x;
    int row  = t >> 5;
    int lane = t & 31;
    int id   = __ldg(&ids[row]);
    float4 v = emb[(size_t)id * 32 + lane];
    ((float4*)g_x)[(size_t)row * 32 + lane] = v;
    float s = v.x + v.y + v.z + v.w;
    float q = v.x*v.x + v.y*v.y + v.z*v.z + v.w*v.w;
    #pragma unroll
    for (int o = 16; o; o >>= 1) {
        s += __shfl_xor_sync(0xffffffffu, s, o);
        q += __shfl_xor_sync(0xffffffffu, q, o);
    }
    float mu  = s * (1.f / 128.f);
    float var = fmaxf(q * (1.f / 128.f) - mu * mu, 0.f);
    float rs  = rsqrtf(var + 1e-5f);
    float4 wv = ((const float4*)w)[lane];
    float4 bv = ((const float4*)bb)[lane];
    uint4 o4;
    o4.x = to_tf32((v.x - mu) * rs * wv.x + bv.x);
    o4.y = to_tf32((v.y - mu) * rs * wv.y + bv.y);
    o4.z = to_tf32((v.z - mu) * rs * wv.z + bv.z);
    o4.w = to_tf32((v.w - mu) * rs * wv.w + bv.w);
    ((uint4*)g_xn)[(size_t)row * 32 + lane] = o4;
}

// ---------------------------------------------------------------------------
// Fused GroupNorm + residual (+ optional LayerNorm->tf32 for next layer).
// ---------------------------------------------------------------------------
template<bool DO_LN>
__global__ void k_gn(const float* __restrict__ gnw,
                     const float* __restrict__ lnw, const float* __restrict__ lnb) {
    const unsigned FULL = 0xffffffffu;
    int t    = blockIdx.x * 256 + threadIdx.x;
    int row  = t >> 5;
    int lane = t & 31;
    float4 hv = ((const float4*)g_h)[(size_t)row * 32 + lane];
    float4 xv = ((const float4*)g_x)[(size_t)row * 32 + lane];
    float s = hv.x + hv.y + hv.z + hv.w;
    float q = hv.x*hv.x + hv.y*hv.y + hv.z*hv.z + hv.w*hv.w;
    #pragma unroll
    for (int o = 1; o < 8; o <<= 1) {         // reduce within 8-lane head group
        s += __shfl_xor_sync(FULL, s, o);
        q += __shfl_xor_sync(FULL, q, o);
    }
    float mu  = s * (1.f / 32.f);
    float var = fmaxf(q * (1.f / 32.f) - mu * mu, 0.f);
    float rs  = rsqrtf(var + 1e-5f);
    float4 gw = ((const float4*)gnw)[lane];
    float4 xp;
    xp.x = xv.x + (hv.x - mu) * rs * gw.x;
    xp.y = xv.y + (hv.y - mu) * rs * gw.y;
    xp.z = xv.z + (hv.z - mu) * rs * gw.z;
    xp.w = xv.w + (hv.w - mu) * rs * gw.w;
    ((float4*)g_x)[(size_t)row * 32 + lane] = xp;

    if (DO_LN) {
        float s2 = xp.x + xp.y + xp.z + xp.w;
        float q2 = xp.x*xp.x + xp.y*xp.y + xp.z*xp.z + xp.w*xp.w;
        #pragma unroll
        for (int o = 16; o; o >>= 1) {
            s2 += __shfl_xor_sync(FULL, s2, o);
            q2 += __shfl_xor_sync(FULL, q2, o);
        }
        float mu2  = s2 * (1.f / 128.f);
        float var2 = fmaxf(q2 * (1.f / 128.f) - mu2 * mu2, 0.f);
        float rs2  = rsqrtf(var2 + 1e-5f);
        float4 wv = ((const float4*)lnw)[lane];
        float4 bv = ((const float4*)lnb)[lane];
        uint4 o4;
        o4.x = to_tf32((xp.x - mu2) * rs2 * wv.x + bv.x);
        o4.y = to_tf32((xp.y - mu2) * rs2 * wv.y + bv.y);
        o4.z = to_tf32((xp.z - mu2) * rs2 * wv.z + bv.z);
        o4.w = to_tf32((xp.w - mu2) * rs2 * wv.w + bv.w);
        ((uint4*)g_xn)[(size_t)row * 32 + lane] = o4;
    }
}

// ---------------------------------------------------------------------------
// tf32 GEMM v2: inputs pre-rounded to tf32 in gmem. Each CTA: bn fixed, loads
// B once, pipelines 4 A tiles (bm) via double-buffered cp.async.
// grid (128, 4): bm = blockIdx.x*4 + i, bn = blockIdx.y. layer selects W half.
// ---------------------------------------------------------------------------
__global__ void __launch_bounds__(256) k_gemm(int layer,
                                              const float* __restrict__ bias) {
    constexpr int STR = 132;                 // padded smem stride (words)
    extern __shared__ unsigned sh[];
    unsigned* Bs = sh;                       // [128][132]
    unsigned* As0 = sh + 128 * STR;          // double buffer
    unsigned* As1 = As0 + 128 * STR;

    int tid = threadIdx.x;
    int bmg = blockIdx.x;                    // group of 4 row tiles
    int bn  = blockIdx.y;                    // gate

    const unsigned* Wg = g_Wt + (size_t)(layer * 4 + bn) * 128 * 128;
    unsigned As0_u = (unsigned)__cvta_generic_to_shared(As0);
    unsigned As1_u = (unsigned)__cvta_generic_to_shared(As1);
    unsigned Bs_u  = (unsigned)__cvta_generic_to_shared(Bs);

    // issue B + A0 (group 0)
    #pragma unroll
    for (int i = 0; i < 16; i++) {
        int e = i * 256 + tid, rr = e >> 5, c4 = e & 31;
        cp_async16(Bs_u + (rr * STR + c4 * 4) * 4, Wg + rr * 128 + c4 * 4);
    }
    {
        const unsigned* Ag = g_xn + (size_t)(bmg * 4 + 0) * 128 * 128;
        #pragma unroll
        for (int i = 0; i < 16; i++) {
            int e = i * 256 + tid, rr = e >> 5, c4 = e & 31;
            cp_async16(As0_u + (rr * STR + c4 * 4) * 4, Ag + rr * 128 + c4 * 4);
        }
    }
    cp_commit();
    // issue A1 (group 1)
    {
        const unsigned* Ag = g_xn + (size_t)(bmg * 4 + 1) * 128 * 128;
        #pragma unroll
        for (int i = 0; i < 16; i++) {
            int e = i * 256 + tid, rr = e >> 5, c4 = e & 31;
            cp_async16(As1_u + (rr * STR + c4 * 4) * 4, Ag + rr * 128 + c4 * 4);
        }
    }
    cp_commit();

    int warp = tid >> 5, lane = tid & 31;
    int wm = warp >> 2, wn = warp & 3;
    int gid = lane >> 2, tg = lane & 3;

    // bias registers (reused across the 4 tiles)
    float bz[4][2];
    #pragma unroll
    for (int j = 0; j < 4; j++) {
        int col = bn * 128 + wn * 32 + j * 8 + tg * 2;
        bz[j][0] = __ldg(&bias[col]);
        bz[j][1] = __ldg(&bias[col + 1]);
    }

    #pragma unroll
    for (int it = 0; it < 4; it++) {
        unsigned* As = (it & 1) ? As1 : As0;
        if (it < 3) cp_wait<1>(); else cp_wait<0>();
        __syncthreads();

        float acc[4][4][4];
        #pragma unroll
        for (int i = 0; i < 4; i++)
            #pragma unroll
            for (int j = 0; j < 4; j++)
                #pragma unroll
                for (int c = 0; c < 4; c++) acc[i][j][c] = 0.f;

        #pragma unroll
        for (int ks = 0; ks < 16; ks++) {
            int k0 = ks * 8 + tg;
            unsigned a[4][4], bf[4][2];
            #pragma unroll
            for (int i = 0; i < 4; i++) {
                int r0 = wm * 64 + i * 16 + gid;
                a[i][0] = As[r0 * STR + k0];
                a[i][1] = As[(r0 + 8) * STR + k0];
                a[i][2] = As[r0 * STR + k0 + 4];
                a[i][3] = As[(r0 + 8) * STR + k0 + 4];
            }
            #pragma unroll
            for (int j = 0; j < 4; j++) {
                int n0 = wn * 32 + j * 8 + gid;
                bf[j][0] = Bs[n0 * STR + k0];
                bf[j][1] = Bs[n0 * STR + k0 + 4];
            }
            #pragma unroll
            for (int i = 0; i < 4; i++)
                #pragma unroll
                for (int j = 0; j < 4; j++)
                    asm volatile(
                        "mma.sync.aligned.m16n8k8.row.col.f32.tf32.tf32.f32 "
                        "{%0,%1,%2,%3}, {%4,%5,%6,%7}, {%8,%9}, {%0,%1,%2,%3};"
                        : "+f"(acc[i][j][0]), "+f"(acc[i][j][1]),
                          "+f"(acc[i][j][2]), "+f"(acc[i][j][3])
                        : "r"(a[i][0]), "r"(a[i][1]), "r"(a[i][2]), "r"(a[i][3]),
                          "r"(bf[j][0]), "r"(bf[j][1]));
        }
        __syncthreads();                      // done reading this A buffer

        if (it + 2 < 4) {                     // refill the buffer just freed
            unsigned dst = (it & 1) ? As1_u : As0_u;
            const unsigned* Ag = g_xn + (size_t)(bmg * 4 + it + 2) * 128 * 128;
            #pragma unroll
            for (int i = 0; i < 16; i++) {
                int e = i * 256 + tid, rr = e >> 5, c4 = e & 31;
                cp_async16(dst + (rr * STR + c4 * 4) * 4, Ag + rr * 128 + c4 * 4);
            }
            cp_commit();
        }

        // epilogue: row r = b*128 + l -> pre[(l*512 + b)*512 + col]
        int bm = bmg * 4 + it;
        #pragma unroll
        for (int i = 0; i < 4; i++) {
            int r0 = bm * 128 + wm * 64 + i * 16 + gid;
            int ra = r0, rb = r0 + 8;
            float* outa = g_pre + ((size_t)(ra & 127) * 512 + (ra >> 7)) * 512;
            float* outb = g_pre + ((size_t)(rb & 127) * 512 + (rb >> 7)) * 512;
            #pragma unroll
            for (int j = 0; j < 4; j++) {
                int col = bn * 128 + wn * 32 + j * 8 + tg * 2;
                *(float2*)&outa[col] = make_float2(acc[i][j][0] + bz[j][0], acc[i][j][1] + bz[j][1]);
                *(float2*)&outb[col] = make_float2(acc[i][j][2] + bz[j][0], acc[i][j][3] + bz[j][1]);
            }
        }
    }
}

// ---------------------------------------------------------------------------
// sLSTM gate math: 5 MUFU (3 ex2 + tanh + rcp)
// ---------------------------------------------------------------------------
__device__ __forceinline__ void gate_step(float ai, float af, float az, float ao,
                                          float& h, float& c, float& n, float& m) {
    float fm = af + m;
    float mn = fmaxf(fm, ai);
    float iv = __expf(ai - mn);
    float fv = __expf(fm - mn);
    float th = tanh_fast(az);
    c = fmaf(fv, c, iv * th);
    n = fmaf(fv, n, iv);
    float eo = __expf(-ao);                   // h = sigmoid(ao) * c / n
    float denom = fmaf(n, eo, n);             //   = c / (n * (1 + e^-ao))
    h = __fdividef(c, denom);
    m = mn;
}

// ---------------------------------------------------------------------------
// Recurrent sLSTM scan v4 (d-split). 256 CTAs x 256 threads, 2 batches/CTA.
// Thread (o, half): holds R for d in [half*16, half*16+16) (32 ull regs),
// accumulates partials for BOTH batches, exchanges scalar partials with its
// in-warp partner (shfl_xor 1), then does gate math for ONE batch.
// h broadcast via smem, one __syncthreads per step.
// ---------------------------------------------------------------------------
__global__ void __launch_bounds__(256, 2) k_scan(const float* __restrict__ R) {
    __shared__ float shh[2][2][4][32];        // [slot][batch][head][oh]

    const unsigned FULL = 0xffffffffu;
    int tid  = threadIdx.x;
    int o    = tid >> 1;                      // output dim 0..127
    int half = tid & 1;                       // d-range half
    int hh   = o >> 5;                        // head
    int oh   = o & 31;                        // dim within head
    int dbase = half * 16;

    int b0 = blockIdx.x * 2;
    int myb = b0 + half;                      // batch this thread gate-steps

    // Rr2[g*8+dp] = ( R[g][hh][dbase+2dp][oh], R[g][hh][dbase+2dp+1][oh] )
    ull Rr2[32];
    #pragma unroll
    for (int g = 0; g < 4; g++)
        #pragma unroll
        for (int dp = 0; dp < 8; dp++) {
            int d0 = dbase + 2 * dp;
            float r0 = __ldg(&R[((g * 4 + hh) * 32 + d0)     * 32 + oh]);
            float r1 = __ldg(&R[((g * 4 + hh) * 32 + d0 + 1) * 32 + oh]);
            Rr2[g * 8 + dp] = pack2(r0, r1);
        }

    float h = 0.f, c = 0.f, n = 0.f, m = 0.f;

    const float* pp = g_pre + (size_t)myb * 512 + o;
    float* ho = g_h + (size_t)myb * kL * kD + o;

    // init slot 0 with zeros
    shh[0][half][hh][oh] = 0.f;
    __syncthreads();

    // prefetch step 0 preactivations
    float p0 = pp[0], p1 = pp[128], p2 = pp[256], p3 = pp[384];

    for (int t = 0; t < kL; t++) {
        int s = t & 1;

        ull accA[4], accB[4];
        #pragma unroll
        for (int g = 0; g < 4; g++) { accA[g] = 0; accB[g] = 0; }

        const float4* hA4 = (const float4*)&shh[s][0][hh][dbase];
        const float4* hB4 = (const float4*)&shh[s][1][hh][dbase];
        #pragma unroll
        for (int j = 0; j < 4; j++) {
            float4 va = hA4[j];
            float4 vb = hB4[j];
            ull a01 = pack2(va.x, va.y), a23 = pack2(va.z, va.w);
            ull b01 = pack2(vb.x, vb.y), b23 = pack2(vb.z, vb.w);
            #pragma unroll
            for (int g = 0; g < 4; g++) {
                accA[g] = ffma2(a01, Rr2[g * 8 + 2 * j],     accA[g]);
                accA[g] = ffma2(a23, Rr2[g * 8 + 2 * j + 1], accA[g]);
                accB[g] = ffma2(b01, Rr2[g * 8 + 2 * j],     accB[g]);
                accB[g] = ffma2(b23, Rr2[g * 8 + 2 * j + 1], accB[g]);
            }
        }

        float pre[4] = {p0, p1, p2, p3};
        if (t + 1 < kL) {
            const float* pn = pp + (size_t)(t + 1) * (kB * 512);
            p0 = pn[0]; p1 = pn[128]; p2 = pn[256]; p3 = pn[384];
        }

        // reduce lo+hi, exchange the "other batch" partials with partner lane
        float g4[4];
        #pragma unroll
        for (int g = 0; g < 4; g++) {
            float al, ah2, bl, bh2;
            unpack2(accA[g], al, ah2); float pA = al + ah2;
            unpack2(accB[g], bl, bh2); float pB = bl + bh2;
            float mine  = half ? pB : pA;     // partial for my batch
            float send  = half ? pA : pB;     // partial for partner's batch
            float recv  = __shfl_xor_sync(FULL, send, 1);
            g4[g] = mine + recv + pre[g];
        }

        gate_step(g4[0], g4[1], g4[2], g4[3], h, c, n, m);

        shh[s ^ 1][half][hh][oh] = h;
        ho[(size_t)t * kD] = h;
        __syncthreads();
    }
}

// ---------------------------------------------------------------------------
// Head: mean over time, then 128->64 ReLU MLP, then 64->2
// ---------------------------------------------------------------------------
__global__ void k_head(const float* __restrict__ w1, const float* __restrict__ b1,
                       const float* __restrict__ w2, const float* __restrict__ b2,
                       float* __restrict__ out) {
    __shared__ float pooled[128];
    __shared__ float hid[64];
    int b = blockIdx.x, o = threadIdx.x;
    const float* xb = g_x + (size_t)b * kL * kD + o;
    float s = 0.f;
    #pragma unroll 8
    for (int t = 0; t < kL; t++) s += xb[(size_t)t * kD];
    pooled[o] = s * (1.f / 128.f);
    __syncthreads();
    if (o < 64) {
        float a = __ldg(&b1[o]);
        const float* wr = w1 + o * 128;
        #pragma unroll
        for (int d = 0; d < 128; d++) a = fmaf(pooled[d], __ldg(&wr[d]), a);
        hid[o] = fmaxf(a, 0.f);
    }
    __syncthreads();
    if (o < 2) {
        float a = __ldg(&b2[o]);
        const float* wr = w2 + o * 64;
        #pragma unroll
        for (int j = 0; j < 64; j++) a = fmaf(hid[j], __ldg(&wr[j]), a);
        out[b * 2 + o] = a;
    }
}

// ---------------------------------------------------------------------------
extern "C" void kernel_launch(void* const* d_in, const int* in_sizes, int n_in,
                              void* d_out, int out_size) {
    const int*   ids  = (const int*)  d_in[0];
    const float* emb  = (const float*)d_in[1];
    const float* ln_w = (const float*)d_in[2];
    const float* ln_b = (const float*)d_in[3];
    const float* Wg   = (const float*)d_in[4];
    const float* Rg   = (const float*)d_in[5];
    const float* bg   = (const float*)d_in[6];
    const float* gn_w = (const float*)d_in[7];
    const float* w1   = (const float*)d_in[8];
    const float* b1   = (const float*)d_in[9];
    const float* w2   = (const float*)d_in[10];
    const float* b2   = (const float*)d_in[11];
    float* out = (float*)d_out;

    constexpr int GEMM_SMEM = 3 * 128 * 132 * 4;   // 202752 B
    cudaFuncSetAttribute(k_gemm, cudaFuncAttributeMaxDynamicSharedMemorySize, GEMM_SMEM);

    const int ROWS = kB * kL;                      // 65536 rows of 128

    k_wcvt<<<128, 256>>>(Wg);                      // both layers' W -> tf32
    k_embed_ln<<<ROWS / 8, 256>>>(ids, (const float4*)emb, ln_w, ln_b);

    // layer 0
    k_gemm<<<dim3(128, 4), 256, GEMM_SMEM>>>(0, bg);
    k_scan<<<256, 256>>>(Rg);
    k_gn<true><<<ROWS / 8, 256>>>(gn_w, ln_w + 128, ln_b + 128);

    // layer 1
    k_gemm<<<dim3(128, 4), 256, GEMM_SMEM>>>(1, bg + 512);
    k_scan<<<256, 256>>>(Rg + (size_t)4 * 4 * 32 * 32);
    k_gn<false><<<ROWS / 8, 256>>>(gn_w + 128, nullptr, nullptr);

    k_head<<<512, 128>>>(w1, b1, w2, b2, out);
}

// round 6
// speedup vs baseline: 1.0259x; 1.0259x over previous
#include <cuda_runtime.h>

// Problem constants
constexpr int kB = 512;   // batch
constexpr int kL = 128;   // seq len
constexpr int kD = 128;   // model dim
// H = 4 heads of 32

// Scratch (device globals: allocation-free rule)
__device__ float    g_x [kB * kL * kD];               // residual stream, [b][t][d]
__device__ unsigned g_xn[kB * kL * kD];               // LN output, tf32 bit patterns
__device__ float    g_h [kB * kL * kD];               // raw scan output h
__device__ float    g_pre[(size_t)kL * kB * 4 * kD];  // gate preacts, [t][b][g][d]
__device__ unsigned g_Wt[2 * 4 * kD * kD];            // W rounded to tf32

typedef unsigned long long ull;

__device__ __forceinline__ ull pack2(float lo, float hi) {
    ull r; asm("mov.b64 %0,{%1,%2};" : "=l"(r) : "f"(lo), "f"(hi)); return r;
}
__device__ __forceinline__ void unpack2(ull v, float& lo, float& hi) {
    asm("mov.b64 {%0,%1},%2;" : "=f"(lo), "=f"(hi) : "l"(v));
}
__device__ __forceinline__ ull ffma2(ull a, ull b, ull c) {
    ull d; asm("fma.rn.f32x2 %0,%1,%2,%3;" : "=l"(d) : "l"(a), "l"(b), "l"(c)); return d;
}
__device__ __forceinline__ float tanh_fast(float x) {
    float y; asm("tanh.approx.f32 %0,%1;" : "=f"(y) : "f"(x)); return y;
}
__device__ __forceinline__ unsigned to_tf32(float f) {
    unsigned u; asm("cvt.rna.tf32.f32 %0, %1;" : "=r"(u) : "f"(f)); return u;
}

__device__ __forceinline__ void cp_async16(unsigned smem, const void* gptr) {
    asm volatile("cp.async.cg.shared.global [%0], [%1], 16;" :: "r"(smem), "l"(gptr));
}
__device__ __forceinline__ void cp_commit() {
    asm volatile("cp.async.commit_group;");
}
template<int N>
__device__ __forceinline__ void cp_wait() {
    asm volatile("cp.async.wait_group %0;" :: "n"(N));
}

// ---------------------------------------------------------------------------
// W -> tf32 pre-round (both layers, once per launch)
// ---------------------------------------------------------------------------
__global__ void k_wcvt(const float* __restrict__ Wg) {
    int i = blockIdx.x * 256 + threadIdx.x;
    #pragma unroll
    for (int j = 0; j < 4; j++) {
        int e = i * 4 + j;
        g_Wt[e] = to_tf32(__ldg(&Wg[e]));
    }
}

// ---------------------------------------------------------------------------
// Fused embedding gather + LayerNorm(layer0). One warp per row of 128.
// ---------------------------------------------------------------------------
__global__ void k_embed_ln(const int* __restrict__ ids, const float4* __restrict__ emb,
                           const float* __restrict__ w, const float* __restrict__ bb) {
    int t    = blockIdx.x * 256 + threadIdx.x;
    int row  = t >> 5;
    int lane = t & 31;
    int id   = __ldg(&ids[row]);
    float4 v = emb[(size_t)id * 32 + lane];
    ((float4*)g_x)[(size_t)row * 32 + lane] = v;
    float s = v.x + v.y + v.z + v.w;
    float q = v.x*v.x + v.y*v.y + v.z*v.z + v.w*v.w;
    #pragma unroll
    for (int o = 16; o; o >>= 1) {
        s += __shfl_xor_sync(0xffffffffu, s, o);
        q += __shfl_xor_sync(0xffffffffu, q, o);
    }
    float mu  = s * (1.f / 128.f);
    float var = fmaxf(q * (1.f / 128.f) - mu * mu, 0.f);
    float rs  = rsqrtf(var + 1e-5f);
    float4 wv = ((const float4*)w)[lane];
    float4 bv = ((const float4*)bb)[lane];
    uint4 o4;
    o4.x = to_tf32((v.x - mu) * rs * wv.x + bv.x);
    o4.y = to_tf32((v.y - mu) * rs * wv.y + bv.y);
    o4.z = to_tf32((v.z - mu) * rs * wv.z + bv.z);
    o4.w = to_tf32((v.w - mu) * rs * wv.w + bv.w);
    ((uint4*)g_xn)[(size_t)row * 32 + lane] = o4;
}

// ---------------------------------------------------------------------------
// Fused GroupNorm + residual (+ optional LayerNorm->tf32 for next layer).
// ---------------------------------------------------------------------------
template<bool DO_LN>
__global__ void k_gn(const float* __restrict__ gnw,
                     const float* __restrict__ lnw, const float* __restrict__ lnb) {
    const unsigned FULL = 0xffffffffu;
    int t    = blockIdx.x * 256 + threadIdx.x;
    int row  = t >> 5;
    int lane = t & 31;
    float4 hv = ((const float4*)g_h)[(size_t)row * 32 + lane];
    float4 xv = ((const float4*)g_x)[(size_t)row * 32 + lane];
    float s = hv.x + hv.y + hv.z + hv.w;
    float q = hv.x*hv.x + hv.y*hv.y + hv.z*hv.z + hv.w*hv.w;
    #pragma unroll
    for (int o = 1; o < 8; o <<= 1) {
        s += __shfl_xor_sync(FULL, s, o);
        q += __shfl_xor_sync(FULL, q, o);
    }
    float mu  = s * (1.f / 32.f);
    float var = fmaxf(q * (1.f / 32.f) - mu * mu, 0.f);
    float rs  = rsqrtf(var + 1e-5f);
    float4 gw = ((const float4*)gnw)[lane];
    float4 xp;
    xp.x = xv.x + (hv.x - mu) * rs * gw.x;
    xp.y = xv.y + (hv.y - mu) * rs * gw.y;
    xp.z = xv.z + (hv.z - mu) * rs * gw.z;
    xp.w = xv.w + (hv.w - mu) * rs * gw.w;
    ((float4*)g_x)[(size_t)row * 32 + lane] = xp;

    if (DO_LN) {
        float s2 = xp.x + xp.y + xp.z + xp.w;
        float q2 = xp.x*xp.x + xp.y*xp.y + xp.z*xp.z + xp.w*xp.w;
        #pragma unroll
        for (int o = 16; o; o >>= 1) {
            s2 += __shfl_xor_sync(FULL, s2, o);
            q2 += __shfl_xor_sync(FULL, q2, o);
        }
        float mu2  = s2 * (1.f / 128.f);
        float var2 = fmaxf(q2 * (1.f / 128.f) - mu2 * mu2, 0.f);
        float rs2  = rsqrtf(var2 + 1e-5f);
        float4 wv = ((const float4*)lnw)[lane];
        float4 bv = ((const float4*)lnb)[lane];
        uint4 o4;
        o4.x = to_tf32((xp.x - mu2) * rs2 * wv.x + bv.x);
        o4.y = to_tf32((xp.y - mu2) * rs2 * wv.y + bv.y);
        o4.z = to_tf32((xp.z - mu2) * rs2 * wv.z + bv.z);
        o4.w = to_tf32((xp.w - mu2) * rs2 * wv.w + bv.w);
        ((uint4*)g_xn)[(size_t)row * 32 + lane] = o4;
    }
}

// ---------------------------------------------------------------------------
// tf32 GEMM v2: inputs pre-rounded to tf32 in gmem. Each CTA: bn fixed, loads
// B once, pipelines 4 A tiles via double-buffered cp.async.
// grid (4, 128): bn = blockIdx.x (fastest -> the 4 CTAs sharing one A group
// are contiguous in bid and co-resident, so A dedups in L2), bmg = blockIdx.y.
// ---------------------------------------------------------------------------
__global__ void __launch_bounds__(256) k_gemm(int layer,
                                              const float* __restrict__ bias) {
    constexpr int STR = 132;                 // padded smem stride (words)
    extern __shared__ unsigned sh[];
    unsigned* Bs = sh;                       // [128][132]
    unsigned* As0 = sh + 128 * STR;          // double buffer
    unsigned* As1 = As0 + 128 * STR;

    int tid = threadIdx.x;
    int bn  = blockIdx.x;                    // gate (fastest)
    int bmg = blockIdx.y;                    // group of 4 row tiles

    const unsigned* Wg = g_Wt + (size_t)(layer * 4 + bn) * 128 * 128;
    unsigned As0_u = (unsigned)__cvta_generic_to_shared(As0);
    unsigned As1_u = (unsigned)__cvta_generic_to_shared(As1);
    unsigned Bs_u  = (unsigned)__cvta_generic_to_shared(Bs);

    // issue B + A0
    #pragma unroll
    for (int i = 0; i < 16; i++) {
        int e = i * 256 + tid, rr = e >> 5, c4 = e & 31;
        cp_async16(Bs_u + (rr * STR + c4 * 4) * 4, Wg + rr * 128 + c4 * 4);
    }
    {
        const unsigned* Ag = g_xn + (size_t)(bmg * 4 + 0) * 128 * 128;
        #pragma unroll
        for (int i = 0; i < 16; i++) {
            int e = i * 256 + tid, rr = e >> 5, c4 = e & 31;
            cp_async16(As0_u + (rr * STR + c4 * 4) * 4, Ag + rr * 128 + c4 * 4);
        }
    }
    cp_commit();
    // issue A1
    {
        const unsigned* Ag = g_xn + (size_t)(bmg * 4 + 1) * 128 * 128;
        #pragma unroll
        for (int i = 0; i < 16; i++) {
            int e = i * 256 + tid, rr = e >> 5, c4 = e & 31;
            cp_async16(As1_u + (rr * STR + c4 * 4) * 4, Ag + rr * 128 + c4 * 4);
        }
    }
    cp_commit();

    int warp = tid >> 5, lane = tid & 31;
    int wm = warp >> 2, wn = warp & 3;
    int gid = lane >> 2, tg = lane & 3;

    float bz[4][2];
    #pragma unroll
    for (int j = 0; j < 4; j++) {
        int col = bn * 128 + wn * 32 + j * 8 + tg * 2;
        bz[j][0] = __ldg(&bias[col]);
        bz[j][1] = __ldg(&bias[col + 1]);
    }

    #pragma unroll
    for (int it = 0; it < 4; it++) {
        unsigned* As = (it & 1) ? As1 : As0;
        if (it < 3) cp_wait<1>(); else cp_wait<0>();
        __syncthreads();

        float acc[4][4][4];
        #pragma unroll
        for (int i = 0; i < 4; i++)
            #pragma unroll
            for (int j = 0; j < 4; j++)
                #pragma unroll
                for (int c = 0; c < 4; c++) acc[i][j][c] = 0.f;

        #pragma unroll
        for (int ks = 0; ks < 16; ks++) {
            int k0 = ks * 8 + tg;
            unsigned a[4][4], bf[4][2];
            #pragma unroll
            for (int i = 0; i < 4; i++) {
                int r0 = wm * 64 + i * 16 + gid;
                a[i][0] = As[r0 * STR + k0];
                a[i][1] = As[(r0 + 8) * STR + k0];
                a[i][2] = As[r0 * STR + k0 + 4];
                a[i][3] = As[(r0 + 8) * STR + k0 + 4];
            }
            #pragma unroll
            for (int j = 0; j < 4; j++) {
                int n0 = wn * 32 + j * 8 + gid;
                bf[j][0] = Bs[n0 * STR + k0];
                bf[j][1] = Bs[n0 * STR + k0 + 4];
            }
            #pragma unroll
            for (int i = 0; i < 4; i++)
                #pragma unroll
                for (int j = 0; j < 4; j++)
                    asm volatile(
                        "mma.sync.aligned.m16n8k8.row.col.f32.tf32.tf32.f32 "
                        "{%0,%1,%2,%3}, {%4,%5,%6,%7}, {%8,%9}, {%0,%1,%2,%3};"
                        : "+f"(acc[i][j][0]), "+f"(acc[i][j][1]),
                          "+f"(acc[i][j][2]), "+f"(acc[i][j][3])
                        : "r"(a[i][0]), "r"(a[i][1]), "r"(a[i][2]), "r"(a[i][3]),
                          "r"(bf[j][0]), "r"(bf[j][1]));
        }
        __syncthreads();

        if (it + 2 < 4) {
            unsigned dst = (it & 1) ? As1_u : As0_u;
            const unsigned* Ag = g_xn + (size_t)(bmg * 4 + it + 2) * 128 * 128;
            #pragma unroll
            for (int i = 0; i < 16; i++) {
                int e = i * 256 + tid, rr = e >> 5, c4 = e & 31;
                cp_async16(dst + (rr * STR + c4 * 4) * 4, Ag + rr * 128 + c4 * 4);
            }
            cp_commit();
        }

        // epilogue: row r = b*128 + l -> pre[(l*512 + b)*512 + col]
        int bm = bmg * 4 + it;
        #pragma unroll
        for (int i = 0; i < 4; i++) {
            int r0 = bm * 128 + wm * 64 + i * 16 + gid;
            int ra = r0, rb = r0 + 8;
            float* outa = g_pre + ((size_t)(ra & 127) * 512 + (ra >> 7)) * 512;
            float* outb = g_pre + ((size_t)(rb & 127) * 512 + (rb >> 7)) * 512;
            #pragma unroll
            for (int j = 0; j < 4; j++) {
                int col = bn * 128 + wn * 32 + j * 8 + tg * 2;
                *(float2*)&outa[col] = make_float2(acc[i][j][0] + bz[j][0], acc[i][j][1] + bz[j][1]);
                *(float2*)&outb[col] = make_float2(acc[i][j][2] + bz[j][0], acc[i][j][3] + bz[j][1]);
            }
        }
    }
}

// ---------------------------------------------------------------------------
// sLSTM gate math: 5 MUFU (3 ex2 + tanh + rcp)
// ---------------------------------------------------------------------------
__device__ __forceinline__ void gate_step(float ai, float af, float az, float ao,
                                          float& h, float& c, float& n, float& m) {
    float fm = af + m;
    float mn = fmaxf(fm, ai);
    float iv = __expf(ai - mn);
    float fv = __expf(fm - mn);
    float th = tanh_fast(az);
    c = fmaf(fv, c, iv * th);
    n = fmaf(fv, n, iv);
    float eo = __expf(-ao);                   // h = sigmoid(ao) * c / n
    float denom = fmaf(n, eo, n);             //   = c / (n * (1 + e^-ao))
    h = __fdividef(c, denom);
    m = mn;
}

// ---------------------------------------------------------------------------
// Recurrent sLSTM scan (round-3 structure + 2-way accumulator trees).
// Grid 128 x 256, 4 batches/CTA, thread = (batch-pair, o), warp = head.
// h broadcast through SMEM (no barriers in the loop). Each gate accumulates
// in TWO independent f32x2 chains (dep latency halved), combined at the end.
// ---------------------------------------------------------------------------
__global__ void __launch_bounds__(256, 1) k_scan(const float* __restrict__ R) {
    __shared__ float shA[2][2][4][32];        // [slot][grp][head][d]
    __shared__ float shB[2][2][4][32];

    int o    = threadIdx.x & 127;            // output dim
    int grp  = threadIdx.x >> 7;             // batch pair within CTA
    int hh   = (threadIdx.x >> 5) & 3;       // head
    int lane = threadIdx.x & 31;

    int b0 = blockIdx.x * 4 + grp * 2;       // batch A; batch B = b0+1

    // Rr2[g*16+dp] = ( R[g][hh][2dp][lane], R[g][hh][2dp+1][lane] )
    ull Rr2[64];
    #pragma unroll
    for (int g = 0; g < 4; g++)
        #pragma unroll
        for (int dp = 0; dp < 16; dp++) {
            float r0 = __ldg(&R[((g * 4 + hh) * 32 + 2 * dp)     * 32 + lane]);
            float r1 = __ldg(&R[((g * 4 + hh) * 32 + 2 * dp + 1) * 32 + lane]);
            Rr2[g * 16 + dp] = pack2(r0, r1);
        }

    float hA = 0.f, cA = 0.f, nA = 0.f, mA = 0.f;
    float hB = 0.f, cB = 0.f, nB = 0.f, mB = 0.f;

    const float* pA = g_pre + (size_t)b0 * 512 + o;
    const float* pB = pA + 512;
    float* hoA = g_h + (size_t)b0 * kL * kD + o;
    float* hoB = hoA + (size_t)kL * kD;

    // prefetch step 0
    float a0 = pA[0], a1 = pA[128], a2 = pA[256], a3 = pA[384];
    float q0 = pB[0], q1 = pB[128], q2 = pB[256], q3 = pB[384];

    for (int t = 0; t < kL; t++) {
        int s = t & 1;
        shA[s][grp][hh][lane] = hA;
        shB[s][grp][hh][lane] = hB;
        __syncwarp();

        // two independent accumulator chains per gate per batch
        ull accA[4][2], accB[4][2];
        #pragma unroll
        for (int g = 0; g < 4; g++) {
            accA[g][0] = 0; accA[g][1] = 0;
            accB[g][0] = 0; accB[g][1] = 0;
        }

        const float4* h4A = (const float4*)shA[s][grp][hh];
        const float4* h4B = (const float4*)shB[s][grp][hh];
        #pragma unroll
        for (int j = 0; j < 8; j++) {
            float4 va = h4A[j];
            float4 vb = h4B[j];
            ull a01 = pack2(va.x, va.y), a23 = pack2(va.z, va.w);
            ull b01 = pack2(vb.x, vb.y), b23 = pack2(vb.z, vb.w);
            int dp = 2 * j;
            #pragma unroll
            for (int g = 0; g < 4; g++) {
                accA[g][0] = ffma2(a01, Rr2[g * 16 + dp],     accA[g][0]);
                accA[g][1] = ffma2(a23, Rr2[g * 16 + dp + 1], accA[g][1]);
                accB[g][0] = ffma2(b01, Rr2[g * 16 + dp],     accB[g][0]);
                accB[g][1] = ffma2(b23, Rr2[g * 16 + dp + 1], accB[g][1]);
            }
        }

        float preA[4] = {a0, a1, a2, a3};
        float preB[4] = {q0, q1, q2, q3};
        if (t + 1 < kL) {
            const float* nA_ = pA + (size_t)(t + 1) * (kB * 512);
            const float* nB_ = pB + (size_t)(t + 1) * (kB * 512);
            a0 = nA_[0]; a1 = nA_[128]; a2 = nA_[256]; a3 = nA_[384];
            q0 = nB_[0]; q1 = nB_[128]; q2 = nB_[256]; q3 = nB_[384];
        }

        float gA[4], gB[4];
        #pragma unroll
        for (int g = 0; g < 4; g++) {
            float l0, h0, l1, h1;
            unpack2(accA[g][0], l0, h0);
            unpack2(accA[g][1], l1, h1);
            gA[g] = (l0 + h0) + (l1 + h1) + preA[g];
            unpack2(accB[g][0], l0, h0);
            unpack2(accB[g][1], l1, h1);
            gB[g] = (l0 + h0) + (l1 + h1) + preB[g];
        }

        gate_step(gA[0], gA[1], gA[2], gA[3], hA, cA, nA, mA);
        gate_step(gB[0], gB[1], gB[2], gB[3], hB, cB, nB, mB);

        hoA[(size_t)t * kD] = hA;
        hoB[(size_t)t * kD] = hB;
    }
}

// ---------------------------------------------------------------------------
// Head: mean over time, then 128->64 ReLU MLP, then 64->2
// ---------------------------------------------------------------------------
__global__ void k_head(const float* __restrict__ w1, const float* __restrict__ b1,
                       const float* __restrict__ w2, const float* __restrict__ b2,
                       float* __restrict__ out) {
    __shared__ float pooled[128];
    __shared__ float hid[64];
    int b = blockIdx.x, o = threadIdx.x;
    const float* xb = g_x + (size_t)b * kL * kD + o;
    float s = 0.f;
    #pragma unroll 8
    for (int t = 0; t < kL; t++) s += xb[(size_t)t * kD];
    pooled[o] = s * (1.f / 128.f);
    __syncthreads();
    if (o < 64) {
        float a = __ldg(&b1[o]);
        const float* wr = w1 + o * 128;
        #pragma unroll
        for (int d = 0; d < 128; d++) a = fmaf(pooled[d], __ldg(&wr[d]), a);
        hid[o] = fmaxf(a, 0.f);
    }
    __syncthreads();
    if (o < 2) {
        float a = __ldg(&b2[o]);
        const float* wr = w2 + o * 64;
        #pragma unroll
        for (int j = 0; j < 64; j++) a = fmaf(hid[j], __ldg(&wr[j]), a);
        out[b * 2 + o] = a;
    }
}

// ---------------------------------------------------------------------------
extern "C" void kernel_launch(void* const* d_in, const int* in_sizes, int n_in,
                              void* d_out, int out_size) {
    const int*   ids  = (const int*)  d_in[0];
    const float* emb  = (const float*)d_in[1];
    const float* ln_w = (const float*)d_in[2];
    const float* ln_b = (const float*)d_in[3];
    const float* Wg   = (const float*)d_in[4];
    const float* Rg   = (const float*)d_in[5];
    const float* bg   = (const float*)d_in[6];
    const float* gn_w = (const float*)d_in[7];
    const float* w1   = (const float*)d_in[8];
    const float* b1   = (const float*)d_in[9];
    const float* w2   = (const float*)d_in[10];
    const float* b2   = (const float*)d_in[11];
    float* out = (float*)d_out;

    constexpr int GEMM_SMEM = 3 * 128 * 132 * 4;   // 202752 B
    cudaFuncSetAttribute(k_gemm, cudaFuncAttributeMaxDynamicSharedMemorySize, GEMM_SMEM);

    const int ROWS = kB * kL;                      // 65536 rows of 128

    k_wcvt<<<128, 256>>>(Wg);                      // both layers' W -> tf32
    k_embed_ln<<<ROWS / 8, 256>>>(ids, (const float4*)emb, ln_w, ln_b);

    // layer 0
    k_gemm<<<dim3(4, 128), 256, GEMM_SMEM>>>(0, bg);
    k_scan<<<128, 256>>>(Rg);
    k_gn<true><<<ROWS / 8, 256>>>(gn_w, ln_w + 128, ln_b + 128);

    // layer 1
    k_gemm<<<dim3(4, 128), 256, GEMM_SMEM>>>(1, bg + 512);
    k_scan<<<128, 256>>>(Rg + (size_t)4 * 4 * 32 * 32);
    k_gn<false><<<ROWS / 8, 256>>>(gn_w + 128, nullptr, nullptr);

    k_head<<<512, 128>>>(w1, b1, w2, b2, out);
}

// round 7
// speedup vs baseline: 1.0367x; 1.0105x over previous
#include <cuda_runtime.h>

// Problem constants
constexpr int kB = 512;   // batch
constexpr int kL = 128;   // seq len
constexpr int kD = 128;   // model dim
// H = 4 heads of 32
constexpr int kTC = 32;   // timesteps per chunk
constexpr int kNC = kL / kTC;  // 4 chunks

// Scratch (device globals: allocation-free rule)
__device__ float    g_x [kB * kL * kD];               // residual stream, [b][t][d]
__device__ unsigned g_xn[kB * kL * kD];               // LN output, tf32 bit patterns
__device__ float    g_h [kB * kL * kD];               // raw scan output h
__device__ float    g_pre[(size_t)kL * kB * 4 * kD];  // gate preacts, [t][b][g][d]
__device__ unsigned g_Wt[2 * 4 * kD * kD];            // W rounded to tf32
__device__ float    g_state[4][kB][kD];               // scan state h,c,n,m between chunks

typedef unsigned long long ull;

__device__ __forceinline__ ull pack2(float lo, float hi) {
    ull r; asm("mov.b64 %0,{%1,%2};" : "=l"(r) : "f"(lo), "f"(hi)); return r;
}
__device__ __forceinline__ void unpack2(ull v, float& lo, float& hi) {
    asm("mov.b64 {%0,%1},%2;" : "=f"(lo), "=f"(hi) : "l"(v));
}
__device__ __forceinline__ ull ffma2(ull a, ull b, ull c) {
    ull d; asm("fma.rn.f32x2 %0,%1,%2,%3;" : "=l"(d) : "l"(a), "l"(b), "l"(c)); return d;
}
__device__ __forceinline__ float tanh_fast(float x) {
    float y; asm("tanh.approx.f32 %0,%1;" : "=f"(y) : "f"(x)); return y;
}
__device__ __forceinline__ unsigned to_tf32(float f) {
    unsigned u; asm("cvt.rna.tf32.f32 %0, %1;" : "=r"(u) : "f"(f)); return u;
}

__device__ __forceinline__ void cp_async16(unsigned smem, const void* gptr) {
    asm volatile("cp.async.cg.shared.global [%0], [%1], 16;" :: "r"(smem), "l"(gptr));
}
__device__ __forceinline__ void cp_commit() {
    asm volatile("cp.async.commit_group;");
}
template<int N>
__device__ __forceinline__ void cp_wait() {
    asm volatile("cp.async.wait_group %0;" :: "n"(N));
}

// ---------------------------------------------------------------------------
// W -> tf32 pre-round (both layers, once per launch)
// ---------------------------------------------------------------------------
__global__ void k_wcvt(const float* __restrict__ Wg) {
    int i = blockIdx.x * 256 + threadIdx.x;
    #pragma unroll
    for (int j = 0; j < 4; j++) {
        int e = i * 4 + j;
        g_Wt[e] = to_tf32(__ldg(&Wg[e]));
    }
}

// ---------------------------------------------------------------------------
// Fused embedding gather + LayerNorm(layer0). One warp per row of 128.
// ---------------------------------------------------------------------------
__global__ void k_embed_ln(const int* __restrict__ ids, const float4* __restrict__ emb,
                           const float* __restrict__ w, const float* __restrict__ bb) {
    int t    = blockIdx.x * 256 + threadIdx.x;
    int row  = t >> 5;
    int lane = t & 31;
    int id   = __ldg(&ids[row]);
    float4 v = emb[(size_t)id * 32 + lane];
    ((float4*)g_x)[(size_t)row * 32 + lane] = v;
    float s = v.x + v.y + v.z + v.w;
    float q = v.x*v.x + v.y*v.y + v.z*v.z + v.w*v.w;
    #pragma unroll
    for (int o = 16; o; o >>= 1) {
        s += __shfl_xor_sync(0xffffffffu, s, o);
        q += __shfl_xor_sync(0xffffffffu, q, o);
    }
    float mu  = s * (1.f / 128.f);
    float var = fmaxf(q * (1.f / 128.f) - mu * mu, 0.f);
    float rs  = rsqrtf(var + 1e-5f);
    float4 wv = ((const float4*)w)[lane];
    float4 bv = ((const float4*)bb)[lane];
    uint4 o4;
    o4.x = to_tf32((v.x - mu) * rs * wv.x + bv.x);
    o4.y = to_tf32((v.y - mu) * rs * wv.y + bv.y);
    o4.z = to_tf32((v.z - mu) * rs * wv.z + bv.z);
    o4.w = to_tf32((v.w - mu) * rs * wv.w + bv.w);
    ((uint4*)g_xn)[(size_t)row * 32 + lane] = o4;
}

// ---------------------------------------------------------------------------
// Fused GroupNorm + residual (+ optional LayerNorm->tf32 for next layer).
// ---------------------------------------------------------------------------
template<bool DO_LN>
__global__ void k_gn(const float* __restrict__ gnw,
                     const float* __restrict__ lnw, const float* __restrict__ lnb) {
    const unsigned FULL = 0xffffffffu;
    int t    = blockIdx.x * 256 + threadIdx.x;
    int row  = t >> 5;
    int lane = t & 31;
    float4 hv = ((const float4*)g_h)[(size_t)row * 32 + lane];
    float4 xv = ((const float4*)g_x)[(size_t)row * 32 + lane];
    float s = hv.x + hv.y + hv.z + hv.w;
    float q = hv.x*hv.x + hv.y*hv.y + hv.z*hv.z + hv.w*hv.w;
    #pragma unroll
    for (int o = 1; o < 8; o <<= 1) {
        s += __shfl_xor_sync(FULL, s, o);
        q += __shfl_xor_sync(FULL, q, o);
    }
    float mu  = s * (1.f / 32.f);
    float var = fmaxf(q * (1.f / 32.f) - mu * mu, 0.f);
    float rs  = rsqrtf(var + 1e-5f);
    float4 gw = ((const float4*)gnw)[lane];
    float4 xp;
    xp.x = xv.x + (hv.x - mu) * rs * gw.x;
    xp.y = xv.y + (hv.y - mu) * rs * gw.y;
    xp.z = xv.z + (hv.z - mu) * rs * gw.z;
    xp.w = xv.w + (hv.w - mu) * rs * gw.w;
    ((float4*)g_x)[(size_t)row * 32 + lane] = xp;

    if (DO_LN) {
        float s2 = xp.x + xp.y + xp.z + xp.w;
        float q2 = xp.x*xp.x + xp.y*xp.y + xp.z*xp.z + xp.w*xp.w;
        #pragma unroll
        for (int o = 16; o; o >>= 1) {
            s2 += __shfl_xor_sync(FULL, s2, o);
            q2 += __shfl_xor_sync(FULL, q2, o);
        }
        float mu2  = s2 * (1.f / 128.f);
        float var2 = fmaxf(q2 * (1.f / 128.f) - mu2 * mu2, 0.f);
        float rs2  = rsqrtf(var2 + 1e-5f);
        float4 wv = ((const float4*)lnw)[lane];
        float4 bv = ((const float4*)lnb)[lane];
        uint4 o4;
        o4.x = to_tf32((xp.x - mu2) * rs2 * wv.x + bv.x);
        o4.y = to_tf32((xp.y - mu2) * rs2 * wv.y + bv.y);
        o4.z = to_tf32((xp.z - mu2) * rs2 * wv.z + bv.z);
        o4.w = to_tf32((xp.w - mu2) * rs2 * wv.w + bv.w);
        ((uint4*)g_xn)[(size_t)row * 32 + lane] = o4;
    }
}

// ---------------------------------------------------------------------------
// tf32 GEMM, per-timestep-chunk. Tile = 128 rows = 4 batches x 32 timesteps.
// grid (4, 32): bn = gate, bmg = group of 4 tiles. B resident per CTA,
// A double-buffered via cp.async.
// ---------------------------------------------------------------------------
__global__ void __launch_bounds__(256) k_gemm_c(int layer, int chunk,
                                                const float* __restrict__ bias) {
    constexpr int STR = 132;                 // padded smem stride (words)
    extern __shared__ unsigned sh[];
    unsigned* Bs = sh;                       // [128][132]
    unsigned* As0 = sh + 128 * STR;          // double buffer
    unsigned* As1 = As0 + 128 * STR;

    int tid = threadIdx.x;
    int bn  = blockIdx.x;                    // gate (fastest -> A dedup in L2)
    int bmg = blockIdx.y;                    // group of 4 tiles

    const unsigned* Wg = g_Wt + (size_t)(layer * 4 + bn) * 128 * 128;
    unsigned As0_u = (unsigned)__cvta_generic_to_shared(As0);
    unsigned As1_u = (unsigned)__cvta_generic_to_shared(As1);
    unsigned Bs_u  = (unsigned)__cvta_generic_to_shared(Bs);
    int l0 = chunk * kTC;

    // A row for tile rt, local row rr:  b = 4*rt + rr/32 ; l = l0 + rr%32
    auto issueA = [&](unsigned dst, int rt) {
        #pragma unroll
        for (int i = 0; i < 16; i++) {
            int e = i * 256 + tid, rr = e >> 5, c4 = e & 31;
            int arow = (4 * rt + (rr >> 5)) * 128 + l0 + (rr & 31);
            cp_async16(dst + (rr * STR + c4 * 4) * 4, g_xn + (size_t)arow * 128 + c4 * 4);
        }
    };

    // issue B + A0
    #pragma unroll
    for (int i = 0; i < 16; i++) {
        int e = i * 256 + tid, rr = e >> 5, c4 = e & 31;
        cp_async16(Bs_u + (rr * STR + c4 * 4) * 4, Wg + rr * 128 + c4 * 4);
    }
    issueA(As0_u, bmg * 4 + 0);
    cp_commit();
    issueA(As1_u, bmg * 4 + 1);
    cp_commit();

    int warp = tid >> 5, lane = tid & 31;
    int wm = warp >> 2, wn = warp & 3;
    int gid = lane >> 2, tg = lane & 3;

    float bz[4][2];
    #pragma unroll
    for (int j = 0; j < 4; j++) {
        int col = bn * 128 + wn * 32 + j * 8 + tg * 2;
        bz[j][0] = __ldg(&bias[col]);
        bz[j][1] = __ldg(&bias[col + 1]);
    }

    #pragma unroll
    for (int it = 0; it < 4; it++) {
        unsigned* As = (it & 1) ? As1 : As0;
        if (it < 3) cp_wait<1>(); else cp_wait<0>();
        __syncthreads();

        float acc[4][4][4];
        #pragma unroll
        for (int i = 0; i < 4; i++)
            #pragma unroll
            for (int j = 0; j < 4; j++)
                #pragma unroll
                for (int c = 0; c < 4; c++) acc[i][j][c] = 0.f;

        #pragma unroll
        for (int ks = 0; ks < 16; ks++) {
            int k0 = ks * 8 + tg;
            unsigned a[4][4], bf[4][2];
            #pragma unroll
            for (int i = 0; i < 4; i++) {
                int r0 = wm * 64 + i * 16 + gid;
                a[i][0] = As[r0 * STR + k0];
                a[i][1] = As[(r0 + 8) * STR + k0];
                a[i][2] = As[r0 * STR + k0 + 4];
                a[i][3] = As[(r0 + 8) * STR + k0 + 4];
            }
            #pragma unroll
            for (int j = 0; j < 4; j++) {
                int n0 = wn * 32 + j * 8 + gid;
                bf[j][0] = Bs[n0 * STR + k0];
                bf[j][1] = Bs[n0 * STR + k0 + 4];
            }
            #pragma unroll
            for (int i = 0; i < 4; i++)
                #pragma unroll
                for (int j = 0; j < 4; j++)
                    asm volatile(
                        "mma.sync.aligned.m16n8k8.row.col.f32.tf32.tf32.f32 "
                        "{%0,%1,%2,%3}, {%4,%5,%6,%7}, {%8,%9}, {%0,%1,%2,%3};"
                        : "+f"(acc[i][j][0]), "+f"(acc[i][j][1]),
                          "+f"(acc[i][j][2]), "+f"(acc[i][j][3])
                        : "r"(a[i][0]), "r"(a[i][1]), "r"(a[i][2]), "r"(a[i][3]),
                          "r"(bf[j][0]), "r"(bf[j][1]));
        }
        __syncthreads();

        if (it + 2 < 4) {
            unsigned dst = (it & 1) ? As1_u : As0_u;
            issueA(dst, bmg * 4 + it + 2);
            cp_commit();
        }

        // epilogue: local row lr -> b = 4*rt + lr/32, l = l0 + lr%32
        int rt = bmg * 4 + it;
        #pragma unroll
        for (int i = 0; i < 4; i++) {
            int lra = wm * 64 + i * 16 + gid;
            int lrb = lra + 8;
            int ba = 4 * rt + (lra >> 5), la = l0 + (lra & 31);
            int bb2 = 4 * rt + (lrb >> 5), lb = l0 + (lrb & 31);
            float* outa = g_pre + ((size_t)la * 512 + ba) * 512;
            float* outb = g_pre + ((size_t)lb * 512 + bb2) * 512;
            #pragma unroll
            for (int j = 0; j < 4; j++) {
                int col = bn * 128 + wn * 32 + j * 8 + tg * 2;
                *(float2*)&outa[col] = make_float2(acc[i][j][0] + bz[j][0], acc[i][j][1] + bz[j][1]);
                *(float2*)&outb[col] = make_float2(acc[i][j][2] + bz[j][0], acc[i][j][3] + bz[j][1]);
            }
        }
    }
}

// ---------------------------------------------------------------------------
// sLSTM gate math: 5 MUFU (3 ex2 + tanh + rcp)
// ---------------------------------------------------------------------------
__device__ __forceinline__ void gate_step(float ai, float af, float az, float ao,
                                          float& h, float& c, float& n, float& m) {
    float fm = af + m;
    float mn = fmaxf(fm, ai);
    float iv = __expf(ai - mn);
    float fv = __expf(fm - mn);
    float th = tanh_fast(az);
    c = fmaf(fv, c, iv * th);
    n = fmaf(fv, n, iv);
    float eo = __expf(-ao);                   // h = sigmoid(ao) * c / n
    float denom = fmaf(n, eo, n);             //   = c / (n * (1 + e^-ao))
    h = __fdividef(c, denom);
    m = mn;
}

// ---------------------------------------------------------------------------
// Recurrent sLSTM scan, one 32-step chunk. Grid 128 x 256, 4 batches/CTA,
// state carried in g_state between chunk launches.
// ---------------------------------------------------------------------------
template<bool FIRST>
__global__ void __launch_bounds__(256, 1) k_scan_c(const float* __restrict__ R, int chunk) {
    __shared__ float shA[2][2][4][32];        // [slot][grp][head][d]
    __shared__ float shB[2][2][4][32];

    int o    = threadIdx.x & 127;            // output dim
    int grp  = threadIdx.x >> 7;             // batch pair within CTA
    int hh   = (threadIdx.x >> 5) & 3;       // head
    int lane = threadIdx.x & 31;

    int b0 = blockIdx.x * 4 + grp * 2;       // batch A; batch B = b0+1

    ull Rr2[64];
    #pragma unroll
    for (int g = 0; g < 4; g++)
        #pragma unroll
        for (int dp = 0; dp < 16; dp++) {
            float r0 = __ldg(&R[((g * 4 + hh) * 32 + 2 * dp)     * 32 + lane]);
            float r1 = __ldg(&R[((g * 4 + hh) * 32 + 2 * dp + 1) * 32 + lane]);
            Rr2[g * 16 + dp] = pack2(r0, r1);
        }

    float hA, cA, nA, mA, hB, cB, nB, mB;
    if (FIRST) {
        hA = cA = nA = mA = 0.f;
        hB = cB = nB = mB = 0.f;
    } else {
        hA = g_state[0][b0][o]; cA = g_state[1][b0][o];
        nA = g_state[2][b0][o]; mA = g_state[3][b0][o];
        hB = g_state[0][b0+1][o]; cB = g_state[1][b0+1][o];
        nB = g_state[2][b0+1][o]; mB = g_state[3][b0+1][o];
    }

    const float* pA = g_pre + (size_t)(chunk * kTC) * (kB * 512) + (size_t)b0 * 512 + o;
    const float* pB = pA + 512;
    float* hoA = g_h + (size_t)b0 * kL * kD + (size_t)(chunk * kTC) * kD + o;
    float* hoB = hoA + (size_t)kL * kD;

    float a0 = pA[0], a1 = pA[128], a2 = pA[256], a3 = pA[384];
    float q0 = pB[0], q1 = pB[128], q2 = pB[256], q3 = pB[384];

    for (int t = 0; t < kTC; t++) {
        int s = t & 1;
        shA[s][grp][hh][lane] = hA;
        shB[s][grp][hh][lane] = hB;
        __syncwarp();

        ull accA[4][2], accB[4][2];
        #pragma unroll
        for (int g = 0; g < 4; g++) {
            accA[g][0] = 0; accA[g][1] = 0;
            accB[g][0] = 0; accB[g][1] = 0;
        }

        const float4* h4A = (const float4*)shA[s][grp][hh];
        const float4* h4B = (const float4*)shB[s][grp][hh];
        #pragma unroll
        for (int j = 0; j < 8; j++) {
            float4 va = h4A[j];
            float4 vb = h4B[j];
            ull a01 = pack2(va.x, va.y), a23 = pack2(va.z, va.w);
            ull b01 = pack2(vb.x, vb.y), b23 = pack2(vb.z, vb.w);
            int dp = 2 * j;
            #pragma unroll
            for (int g = 0; g < 4; g++) {
                accA[g][0] = ffma2(a01, Rr2[g * 16 + dp],     accA[g][0]);
                accA[g][1] = ffma2(a23, Rr2[g * 16 + dp + 1], accA[g][1]);
                accB[g][0] = ffma2(b01, Rr2[g * 16 + dp],     accB[g][0]);
                accB[g][1] = ffma2(b23, Rr2[g * 16 + dp + 1], accB[g][1]);
            }
        }

        float preA[4] = {a0, a1, a2, a3};
        float preB[4] = {q0, q1, q2, q3};
        if (t + 1 < kTC) {
            const float* nA_ = pA + (size_t)(t + 1) * (kB * 512);
            const float* nB_ = pB + (size_t)(t + 1) * (kB * 512);
            a0 = nA_[0]; a1 = nA_[128]; a2 = nA_[256]; a3 = nA_[384];
            q0 = nB_[0]; q1 = nB_[128]; q2 = nB_[256]; q3 = nB_[384];
        }

        float gA[4], gB[4];
        #pragma unroll
        for (int g = 0; g < 4; g++) {
            float l0, h0, l1, h1;
            unpack2(accA[g][0], l0, h0);
            unpack2(accA[g][1], l1, h1);
            gA[g] = (l0 + h0) + (l1 + h1) + preA[g];
            unpack2(accB[g][0], l0, h0);
            unpack2(accB[g][1], l1, h1);
            gB[g] = (l0 + h0) + (l1 + h1) + preB[g];
        }

        gate_step(gA[0], gA[1], gA[2], gA[3], hA, cA, nA, mA);
        gate_step(gB[0], gB[1], gB[2], gB[3], hB, cB, nB, mB);

        hoA[(size_t)t * kD] = hA;
        hoB[(size_t)t * kD] = hB;
    }

    g_state[0][b0][o] = hA; g_state[1][b0][o] = cA;
    g_state[2][b0][o] = nA; g_state[3][b0][o] = mA;
    g_state[0][b0+1][o] = hB; g_state[1][b0+1][o] = cB;
    g_state[2][b0+1][o] = nB; g_state[3][b0+1][o] = mB;
}

// ---------------------------------------------------------------------------
// Head: mean over time, then 128->64 ReLU MLP, then 64->2
// ---------------------------------------------------------------------------
__global__ void k_head(const float* __restrict__ w1, const float* __restrict__ b1,
                       const float* __restrict__ w2, const float* __restrict__ b2,
                       float* __restrict__ out) {
    __shared__ float pooled[128];
    __shared__ float hid[64];
    int b = blockIdx.x, o = threadIdx.x;
    const float* xb = g_x + (size_t)b * kL * kD + o;
    float s = 0.f;
    #pragma unroll 8
    for (int t = 0; t < kL; t++) s += xb[(size_t)t * kD];
    pooled[o] = s * (1.f / 128.f);
    __syncthreads();
    if (o < 64) {
        float a = __ldg(&b1[o]);
        const float* wr = w1 + o * 128;
        #pragma unroll
        for (int d = 0; d < 128; d++) a = fmaf(pooled[d], __ldg(&wr[d]), a);
        hid[o] = fmaxf(a, 0.f);
    }
    __syncthreads();
    if (o < 2) {
        float a = __ldg(&b2[o]);
        const float* wr = w2 + o * 64;
        #pragma unroll
        for (int j = 0; j < 64; j++) a = fmaf(hid[j], __ldg(&wr[j]), a);
        out[b * 2 + o] = a;
    }
}

// ---------------------------------------------------------------------------
extern "C" void kernel_launch(void* const* d_in, const int* in_sizes, int n_in,
                              void* d_out, int out_size) {
    const int*   ids  = (const int*)  d_in[0];
    const float* emb  = (const float*)d_in[1];
    const float* ln_w = (const float*)d_in[2];
    const float* ln_b = (const float*)d_in[3];
    const float* Wg   = (const float*)d_in[4];
    const float* Rg   = (const float*)d_in[5];
    const float* bg   = (const float*)d_in[6];
    const float* gn_w = (const float*)d_in[7];
    const float* w1   = (const float*)d_in[8];
    const float* b1   = (const float*)d_in[9];
    const float* w2   = (const float*)d_in[10];
    const float* b2   = (const float*)d_in[11];
    float* out = (float*)d_out;

    // one-time stream/event creation (host resources only; no device memory)
    static cudaStream_t s1 = nullptr;
    static cudaEvent_t evXn[2];
    static cudaEvent_t evG[2][kNC];
    if (!s1) {
        cudaStreamCreateWithFlags(&s1, cudaStreamNonBlocking);
        for (int l = 0; l < 2; l++) {
            cudaEventCreateWithFlags(&evXn[l], cudaEventDisableTiming);
            for (int c = 0; c < kNC; c++)
                cudaEventCreateWithFlags(&evG[l][c], cudaEventDisableTiming);
        }
    }

    constexpr int GEMM_SMEM = 3 * 128 * 132 * 4;   // 202752 B
    cudaFuncSetAttribute(k_gemm_c, cudaFuncAttributeMaxDynamicSharedMemorySize, GEMM_SMEM);

    const int ROWS = kB * kL;                      // 65536 rows of 128

    k_wcvt<<<128, 256, 0, s1>>>(Wg);               // W -> tf32 on side stream
    k_embed_ln<<<ROWS / 8, 256>>>(ids, (const float4*)emb, ln_w, ln_b);
    cudaEventRecord(evXn[0], 0);

    for (int l = 0; l < 2; l++) {
        const float* Rl = Rg + (size_t)l * 4 * 4 * 32 * 32;
        const float* bl = bg + l * 512;

        cudaStreamWaitEvent(s1, evXn[l], 0);
        for (int c = 0; c < kNC; c++) {
            k_gemm_c<<<dim3(4, 32), 256, GEMM_SMEM, s1>>>(l, c, bl);
            cudaEventRecord(evG[l][c], s1);
        }
        for (int c = 0; c < kNC; c++) {
            cudaStreamWaitEvent(0, evG[l][c], 0);
            if (c == 0) k_scan_c<true ><<<128, 256>>>(Rl, c);
            else        k_scan_c<false><<<128, 256>>>(Rl, c);
        }
        if (l == 0) {
            k_gn<true ><<<ROWS / 8, 256>>>(gn_w, ln_w + 128, ln_b + 128);
            cudaEventRecord(evXn[1], 0);
        } else {
            k_gn<false><<<ROWS / 8, 256>>>(gn_w + 128, nullptr, nullptr);
        }
    }

    k_head<<<512, 128>>>(w1, b1, w2, b2, out);
}